// round 1
// baseline (speedup 1.0000x reference)
#include <cuda_runtime.h>
#include <math.h>

#define ITEM_NUM 50000
#define EMBED    256
#define HIDDEN   128
#define BATCH    4096
#define HIST     50
#define KN       10
#define D4       64
#define D2       128

#define TB       512      // main kernel threads
#define CH       5        // h per chunk
#define NCHUNK   10       // 50 / CH
#define GRID_MAIN 148     // persistent blocks (B200 SM count)

// ---------------- device scratch (static allocation only) ----------------
__device__ float  g_region_in [ITEM_NUM * D4];
__device__ float  g_region_out[ITEM_NUM * D4];
__device__ float2 g_permW[32 * TB];   // [r][t] : thread t's r-th f32x2 of W1

// packed fp32x2 FMA (sm_100a)
__device__ __forceinline__ void ffma2(float2 &d, const float2 &a, const float2 &b) {
    asm("fma.rn.f32x2 %0, %1, %2, %0;"
        : "+l"(reinterpret_cast<unsigned long long &>(d))
        : "l"(reinterpret_cast<const unsigned long long &>(a)),
          "l"(reinterpret_cast<const unsigned long long &>(b)));
}

// ---------------- kernel 0: permute W1 for coalesced register fill -------
// main kernel thread t: jp = t & 63, eo = t >> 6.
// r < 16  -> j = jp,      m = r
// r >= 16 -> j = jp + 64, m = r - 16
// value = W1 (row-major 128x256) viewed as float2[128][128] at [j][eo*16+m]
__global__ void permw_kernel(const float* __restrict__ W1) {
    const float2* Wf2 = reinterpret_cast<const float2*>(W1);
    int t  = threadIdx.x;
    int jp = t & 63;
    int eo = t >> 6;
    #pragma unroll
    for (int r = 0; r < 32; r++) {
        int j = (r < 16) ? jp : (jp + 64);
        int m = r & 15;
        g_permW[r * TB + t] = Wf2[j * 128 + eo * 16 + m];
    }
}

// ---------------- kernel A: region self-attention ------------------------
// 2 items per 128-thread block; 64 threads per item (d = dim index).
// Reproduces the reference's reshape-based keys:
//   scores[k] = (1/8) * sum_i q[i] * kv_flat[i*10 + k]
__global__ void region_kernel(const int*   __restrict__ near_pois,
                              const float* __restrict__ E_in,
                              const float* __restrict__ E_out) {
    __shared__ float in_s [2][640];
    __shared__ float out_s[2][640];
    __shared__ float wo_s [2][10];
    __shared__ float wi_s [2][10];
    __shared__ int   idx_s[2][10];

    int li = threadIdx.x >> 6;   // item slot in block
    int d  = threadIdx.x & 63;   // dim
    int n  = blockIdx.x * 2 + li;   // 25000 * 2 == 50000 exactly

    if (d < KN) idx_s[li][d] = near_pois[n * KN + d];
    __syncthreads();

    #pragma unroll
    for (int k = 0; k < KN; k++) {
        int idx = idx_s[li][k];
        in_s [li][k * 64 + d] = E_in [idx * 64 + d];
        out_s[li][k * 64 + d] = E_out[idx * 64 + d];
    }
    __syncthreads();

    if (d < KN) {
        // region_out scores: q = ingoing row0, keys = reshaped outgoing
        float s = 0.f;
        #pragma unroll
        for (int i = 0; i < 64; i++) s += in_s[li][i] * out_s[li][i * KN + d];
        wo_s[li][d] = expf(s * 0.125f);
    } else if (d >= 32 && d < 32 + KN) {
        int k = d - 32;
        float s = 0.f;
        #pragma unroll
        for (int i = 0; i < 64; i++) s += out_s[li][i] * in_s[li][i * KN + k];
        wi_s[li][k] = expf(s * 0.125f);
    }
    __syncthreads();

    float so = 0.f, si = 0.f;
    #pragma unroll
    for (int k = 0; k < KN; k++) { so += wo_s[li][k]; si += wi_s[li][k]; }
    float ro = 0.f, ri = 0.f;
    #pragma unroll
    for (int k = 0; k < KN; k++) {
        ro += wo_s[li][k] * out_s[li][k * 64 + d];
        ri += wi_s[li][k] * in_s [li][k * 64 + d];
    }
    g_region_out[n * 64 + d] = ro / so;
    g_region_in [n * 64 + d] = ri / si;
}

// ---------------- kernel B: main scoring (persistent) --------------------
struct SmemB {
    float x[HIST][EMBED];              // 51200 B : hist ⊙ targ
    float partial[8][CH][HIDDEN];      // 20480 B : per-eo partial dot
    float redv[CH][HIDDEN];            //  2560 B : relu(h1)*W2
    float targ[EMBED];
    float b1v[HIDDEN];
    float w2v[HIDDEN];
    float dots[HIST];
    float scores[HIST];
    int   idx[HIST];
};

__global__ __launch_bounds__(TB, 1)
void main_kernel(const int*   __restrict__ history,
                 const int*   __restrict__ target,
                 const float* __restrict__ E_hist,
                 const float* __restrict__ E_targ,
                 const float* __restrict__ b1,
                 const float* __restrict__ W2,
                 float*       __restrict__ out) {
    extern __shared__ char smem_raw[];
    SmemB* s = reinterpret_cast<SmemB*>(smem_raw);

    const int t  = threadIdx.x;
    const int jp = t & 63;     // thread owns j = jp and j = jp + 64
    const int eo = t >> 6;     // e-range [eo*32, eo*32+32)

    // W1 slice in registers, coalesced fill from permuted copy
    float2 Wreg[32];
    #pragma unroll
    for (int r = 0; r < 32; r++) Wreg[r] = g_permW[r * TB + t];

    if (t < HIDDEN) { s->b1v[t] = b1[t]; s->w2v[t] = W2[t]; }
    __syncthreads();

    for (int b = blockIdx.x; b < BATCH; b += gridDim.x) {
        const int tg = target[b];

        // ---- phase 1: indices + targ vector ----
        if (t < HIST) s->idx[t] = history[b * HIST + t];
        if (t < 128)                 s->targ[t] = E_targ[tg * 128 + t];
        else if (t < 192)            s->targ[t] = g_region_out[tg * 64 + (t - 128)];
        else if (t < 256)            s->targ[t] = g_region_in [tg * 64 + (t - 192)];
        __syncthreads();

        // ---- phase 2: build x = hist ⊙ targ ----
        #pragma unroll 5
        for (int it = 0; it < 25; it++) {
            int h = it * 2 + (t >> 8);
            int e = t & 255;
            int idx = s->idx[h];
            float hv;
            if (e < 128)      hv = E_hist[idx * 128 + e];
            else if (e < 192) hv = g_region_in [idx * 64 + (e - 128)];
            else              hv = g_region_out[idx * 64 + (e - 192)];
            s->x[h][e] = hv * s->targ[e];
        }
        __syncthreads();

        // ---- phase 3: dots[h] = sum_e x[h][e]  (one warp strides h) ----
        {
            int w = t >> 5, lane = t & 31;
            for (int h = w; h < HIST; h += 16) {
                const float4* row = reinterpret_cast<const float4*>(s->x[h]);
                float4 a = row[lane], c = row[lane + 32];
                float v = a.x + a.y + a.z + a.w + c.x + c.y + c.z + c.w;
                #pragma unroll
                for (int o = 16; o; o >>= 1) v += __shfl_xor_sync(0xffffffffu, v, o);
                if (lane == 0) s->dots[h] = v;
            }
        }

        // ---- phase 4: MLP chunks (FFMA2 mainloop) ----
        for (int c = 0; c < NCHUNK; c++) {
            const int hbase = c * CH;
            float2 acc[CH][2];
            #pragma unroll
            for (int hh = 0; hh < CH; hh++) {
                acc[hh][0] = make_float2(0.f, 0.f);
                acc[hh][1] = make_float2(0.f, 0.f);
            }
            #pragma unroll
            for (int m = 0; m < 16; m++) {
                const float2 w0 = Wreg[m];
                const float2 w1 = Wreg[16 + m];
                const int e2 = eo * 16 + m;
                #pragma unroll
                for (int hh = 0; hh < CH; hh++) {
                    float2 xv = *reinterpret_cast<const float2*>(&s->x[hbase + hh][2 * e2]);
                    ffma2(acc[hh][0], w0, xv);
                    ffma2(acc[hh][1], w1, xv);
                }
            }
            #pragma unroll
            for (int hh = 0; hh < CH; hh++) {
                s->partial[eo][hh][jp]      = acc[hh][0].x + acc[hh][0].y;
                s->partial[eo][hh][jp + 64] = acc[hh][1].x + acc[hh][1].y;
            }
            __syncthreads();

            // reduce over eo, add bias, relu, scale by W2
            for (int o = t; o < CH * HIDDEN; o += TB) {
                int hh = o >> 7, j = o & 127;
                float sum = s->b1v[j];
                #pragma unroll
                for (int q = 0; q < 8; q++) sum += s->partial[q][hh][j];
                s->redv[hh][j] = fmaxf(sum, 0.f) * s->w2v[j];
            }
            __syncthreads();

            if (t < CH * 32) {
                int hh = t >> 5, lane = t & 31;
                float v = s->redv[hh][lane] + s->redv[hh][lane + 32]
                        + s->redv[hh][lane + 64] + s->redv[hh][lane + 96];
                #pragma unroll
                for (int o = 16; o; o >>= 1) v += __shfl_xor_sync(0xffffffffu, v, o);
                if (lane == 0) s->scores[hbase + hh] = v;
            }
            __syncthreads();
        }

        // ---- phase 5: masked exp weighting + prediction ----
        if (t < 32) {
            float num = 0.f, den = 0.f;
            for (int h = t; h < HIST; h += 32) {
                float e = expf(s->scores[h]);
                if (s->idx[h] == tg) e = 0.f;   // mask: history == target
                num += e * s->dots[h];
                den += e;
            }
            #pragma unroll
            for (int o = 16; o; o >>= 1) {
                num += __shfl_xor_sync(0xffffffffu, num, o);
                den += __shfl_xor_sync(0xffffffffu, den, o);
            }
            if (t == 0) {
                float pred = num / sqrtf(den);      // BETA = 0.5
                out[b] = 1.f / (1.f + expf(-pred));
            }
        }
        __syncthreads();   // protect smem reuse for next b
    }
}

// ---------------- launch ----------------
extern "C" void kernel_launch(void* const* d_in, const int* in_sizes, int n_in,
                              void* d_out, int out_size) {
    const int*   history = (const int*)  d_in[0];
    const int*   target  = (const int*)  d_in[1];
    const int*   near_p  = (const int*)  d_in[2];
    // d_in[3] = target_region (unused by the reference)
    const float* E_in    = (const float*)d_in[4];
    const float* E_out   = (const float*)d_in[5];
    const float* E_hist  = (const float*)d_in[6];
    const float* E_targ  = (const float*)d_in[7];
    const float* W1      = (const float*)d_in[8];
    const float* b1      = (const float*)d_in[9];
    const float* W2      = (const float*)d_in[10];
    float* out = (float*)d_out;

    permw_kernel<<<1, TB>>>(W1);
    region_kernel<<<ITEM_NUM / 2, 128>>>(near_p, E_in, E_out);

    cudaFuncSetAttribute(main_kernel,
                         cudaFuncAttributeMaxDynamicSharedMemorySize,
                         (int)sizeof(SmemB));
    main_kernel<<<GRID_MAIN, TB, sizeof(SmemB)>>>(history, target, E_hist, E_targ,
                                                  b1, W2, out);
}

// round 4
// speedup vs baseline: 2.9601x; 2.9601x over previous
#include <cuda_runtime.h>
#include <cuda_bf16.h>
#include <cstdint>
#include <math.h>

#define ITEM_NUM 50000
#define BATCH    4096
#define HIST     50
#define KN       10
#define TB       512
#define GRID_MAIN 148
#define NPAIR    (BATCH / 2)

// bf16 tile pitch: 264 bf16 = 528 B per row (16B-aligned, 132 words ≡ 4 mod 32
// banks -> ldmatrix 8-row phases are bank-conflict-free)
#define PITCH_B  528

// ---------------- device scratch ----------------
__device__ float g_region_in [ITEM_NUM * 64];
__device__ float g_region_out[ITEM_NUM * 64];

// ---------------- PTX helpers ----------------
__device__ __forceinline__ uint32_t smem_u32(const void* p) {
    uint32_t a;
    asm("{ .reg .u64 t; cvta.to.shared.u64 t, %1; cvt.u32.u64 %0, t; }" : "=r"(a) : "l"(p));
    return a;
}

__device__ __forceinline__ void ldmatrix_x4(uint32_t& r0, uint32_t& r1,
                                            uint32_t& r2, uint32_t& r3,
                                            uint32_t addr) {
    asm volatile("ldmatrix.sync.aligned.m8n8.x4.shared.b16 {%0,%1,%2,%3}, [%4];"
                 : "=r"(r0), "=r"(r1), "=r"(r2), "=r"(r3) : "r"(addr));
}

__device__ __forceinline__ void mma_16816(float& d0, float& d1, float& d2, float& d3,
                                          uint32_t a0, uint32_t a1, uint32_t a2, uint32_t a3,
                                          uint32_t b0, uint32_t b1) {
    asm volatile(
        "mma.sync.aligned.m16n8k16.row.col.f32.bf16.bf16.f32 "
        "{%0,%1,%2,%3}, {%4,%5,%6,%7}, {%8,%9}, {%0,%1,%2,%3};"
        : "+f"(d0), "+f"(d1), "+f"(d2), "+f"(d3)
        : "r"(a0), "r"(a1), "r"(a2), "r"(a3), "r"(b0), "r"(b1));
}

// ---------------- kernel A: region self-attention (passed in R1) ---------
__global__ void region_kernel(const int*   __restrict__ near_pois,
                              const float* __restrict__ E_in,
                              const float* __restrict__ E_out) {
    __shared__ float in_s [2][640];
    __shared__ float out_s[2][640];
    __shared__ float wo_s [2][10];
    __shared__ float wi_s [2][10];
    __shared__ int   idx_s[2][10];

    int li = threadIdx.x >> 6;
    int d  = threadIdx.x & 63;
    int n  = blockIdx.x * 2 + li;

    if (d < KN) idx_s[li][d] = near_pois[n * KN + d];
    __syncthreads();

    #pragma unroll
    for (int k = 0; k < KN; k++) {
        int idx = idx_s[li][k];
        in_s [li][k * 64 + d] = E_in [idx * 64 + d];
        out_s[li][k * 64 + d] = E_out[idx * 64 + d];
    }
    __syncthreads();

    if (d < KN) {
        float s = 0.f;
        #pragma unroll
        for (int i = 0; i < 64; i++) s += in_s[li][i] * out_s[li][i * KN + d];
        wo_s[li][d] = expf(s * 0.125f);
    } else if (d >= 32 && d < 32 + KN) {
        int k = d - 32;
        float s = 0.f;
        #pragma unroll
        for (int i = 0; i < 64; i++) s += out_s[li][i] * in_s[li][i * KN + k];
        wi_s[li][k] = expf(s * 0.125f);
    }
    __syncthreads();

    float so = 0.f, si = 0.f;
    #pragma unroll
    for (int k = 0; k < KN; k++) { so += wo_s[li][k]; si += wi_s[li][k]; }
    float ro = 0.f, ri = 0.f;
    #pragma unroll
    for (int k = 0; k < KN; k++) {
        ro += wo_s[li][k] * out_s[li][k * 64 + d];
        ri += wi_s[li][k] * in_s [li][k * 64 + d];
    }
    g_region_out[n * 64 + d] = ro / so;
    g_region_in [n * 64 + d] = ri / si;
}

// ---------------- main kernel: warp-MMA GEMM path -------------------------
// smem: X bf16 [128][PITCH], W bf16 [128][PITCH], then Aux
#define SM_X   0
#define SM_W   (128 * PITCH_B)              // 67584
#define SM_AUX (2 * 128 * PITCH_B)          // 135168

struct Aux {
    float targ[2][256];
    float b1v[128];
    float w2v[128];
    float part[4][128];
    float dots[128];
    int   idxm[128];
    int   tgv[2];
    float scores[128];
};
#define SMEM_TOTAL (SM_AUX + (int)sizeof(Aux))

__global__ __launch_bounds__(TB, 1)
void main_kernel(const int*   __restrict__ history,
                 const int*   __restrict__ target,
                 const float* __restrict__ E_hist,
                 const float* __restrict__ E_targ,
                 const float* __restrict__ W1,
                 const float* __restrict__ b1,
                 const float* __restrict__ W2,
                 float*       __restrict__ out) {
    extern __shared__ char sm[];
    Aux* s = reinterpret_cast<Aux*>(sm + SM_AUX);
    const uint32_t sbase = smem_u32(sm);

    const int t    = threadIdx.x;
    const int wid  = t >> 5;
    const int lane = t & 31;
    const int m    = t >> 2;      // gather row (0..127)
    const int q    = t & 3;       // e-quarter (64 floats)
    const int r    = m >> 6;      // batch slot in pair
    const int h    = m & 63;
    const bool hvalid = (h < HIST);

    const int wm = wid & 3;       // warp row-tile (32 rows)
    const int wn = wid >> 2;      // warp col-tile (32 cols)

    // ---- prologue ----
    {   // zero X (pad rows stay zero forever)
        uint4 z = make_uint4(0, 0, 0, 0);
        for (int i = t; i < 128 * PITCH_B / 16; i += TB)
            reinterpret_cast<uint4*>(sm + SM_X)[i] = z;
    }
    {   // W1 -> bf16 smem, row j = m, quarter q
        const float4* src4 = reinterpret_cast<const float4*>(W1 + m * 256 + q * 64);
        char* dst = sm + SM_W + m * PITCH_B + q * 128;
        #pragma unroll
        for (int g = 0; g < 8; g++) {
            float4 a = src4[g * 2], b = src4[g * 2 + 1];
            __nv_bfloat162 p0 = __floats2bfloat162_rn(a.x, a.y);
            __nv_bfloat162 p1 = __floats2bfloat162_rn(a.z, a.w);
            __nv_bfloat162 p2 = __floats2bfloat162_rn(b.x, b.y);
            __nv_bfloat162 p3 = __floats2bfloat162_rn(b.z, b.w);
            uint4 u;
            u.x = *reinterpret_cast<uint32_t*>(&p0);
            u.y = *reinterpret_cast<uint32_t*>(&p1);
            u.z = *reinterpret_cast<uint32_t*>(&p2);
            u.w = *reinterpret_cast<uint32_t*>(&p3);
            *reinterpret_cast<uint4*>(dst + g * 16) = u;
        }
    }
    if (t < 128) { s->b1v[t] = b1[t]; s->w2v[t] = W2[t]; }
    __syncthreads();

    // ldmatrix source addresses (k0 = 0; advance 32 B per k-step)
    // A x4: mat0 rows 0..7 @k0 | mat1 rows 8..15 @k0 | mat2 rows 0..7 @k0+8 | mat3 rows 8..15 @k0+8
    const int a_row = wm * 32 + ((lane >> 3) & 1) * 8 + (lane & 7);
    const uint32_t a_addr0 = sbase + SM_X + a_row * PITCH_B + (lane >> 4) * 16;
    // B x4: mat0 n0..7 @k0 | mat1 n0..7 @k0+8 | mat2 n8..15 @k0 | mat3 n8..15 @k0+8
    const int b_row = wn * 32 + (lane >> 4) * 8 + (lane & 7);
    const uint32_t b_addr0 = sbase + SM_W + b_row * PITCH_B + ((lane >> 3) & 1) * 16;

    for (int p = blockIdx.x; p < NPAIR; p += gridDim.x) {
        // ---- phase 0: targets + history indices ----
        if (t < 2) s->tgv[t] = target[p * 2 + t];
        for (int v = t; v < 512; v += TB) {
            int rr = v >> 8, e = v & 255;
            int tg = target[p * 2 + rr];
            float val;
            if (e < 128)      val = E_targ[tg * 128 + e];
            else if (e < 192) val = g_region_out[tg * 64 + (e - 128)];
            else              val = g_region_in [tg * 64 + (e - 192)];
            s->targ[rr][e] = val;
        }
        int idx = 0;
        if (q == 0 && hvalid) idx = history[(p * 2 + r) * HIST + h];
        idx = __shfl_sync(0xffffffffu, idx, lane & ~3);
        if (q == 0) s->idxm[m] = idx;
        __syncthreads();

        // ---- phase 1: gather X = hist ⊙ targ -> bf16 smem; fp32 dots ----
        float dotp = 0.f;
        if (hvalid) {
            const float* srcp;
            if (q < 2)       srcp = E_hist + idx * 128 + q * 64;
            else if (q == 2) srcp = g_region_in  + idx * 64;
            else             srcp = g_region_out + idx * 64;
            const float4* src4 = reinterpret_cast<const float4*>(srcp);
            const float4* tg4  = reinterpret_cast<const float4*>(&s->targ[r][q * 64]);
            char* dst = sm + SM_X + m * PITCH_B + q * 128;
            #pragma unroll
            for (int g = 0; g < 8; g++) {
                float4 a = src4[g * 2], b = src4[g * 2 + 1];
                float4 ta = tg4[g * 2], tb = tg4[g * 2 + 1];
                float x0 = a.x * ta.x, x1 = a.y * ta.y, x2 = a.z * ta.z, x3 = a.w * ta.w;
                float x4 = b.x * tb.x, x5 = b.y * tb.y, x6 = b.z * tb.z, x7 = b.w * tb.w;
                dotp += (x0 + x1) + (x2 + x3) + (x4 + x5) + (x6 + x7);
                __nv_bfloat162 p0 = __floats2bfloat162_rn(x0, x1);
                __nv_bfloat162 p1 = __floats2bfloat162_rn(x2, x3);
                __nv_bfloat162 p2 = __floats2bfloat162_rn(x4, x5);
                __nv_bfloat162 p3 = __floats2bfloat162_rn(x6, x7);
                uint4 u;
                u.x = *reinterpret_cast<uint32_t*>(&p0);
                u.y = *reinterpret_cast<uint32_t*>(&p1);
                u.z = *reinterpret_cast<uint32_t*>(&p2);
                u.w = *reinterpret_cast<uint32_t*>(&p3);
                *reinterpret_cast<uint4*>(dst + g * 16) = u;
            }
        }
        dotp += __shfl_xor_sync(0xffffffffu, dotp, 1);
        dotp += __shfl_xor_sync(0xffffffffu, dotp, 2);
        if (q == 0) s->dots[m] = dotp;
        __syncthreads();

        // ---- phase 2: warp MMA, D tile 32x32 in registers ----
        float d[2][4][4];
        #pragma unroll
        for (int mt = 0; mt < 2; mt++)
            #pragma unroll
            for (int nt = 0; nt < 4; nt++)
                #pragma unroll
                for (int i = 0; i < 4; i++) d[mt][nt][i] = 0.f;

        #pragma unroll
        for (int ks = 0; ks < 16; ks++) {
            const uint32_t koff = ks * 32;
            uint32_t a0[4], a1[4], b0[4], b1r[4];
            ldmatrix_x4(a0[0], a0[1], a0[2], a0[3], a_addr0 + koff);
            ldmatrix_x4(a1[0], a1[1], a1[2], a1[3], a_addr0 + 16 * PITCH_B + koff);
            ldmatrix_x4(b0[0], b0[1], b0[2], b0[3], b_addr0 + koff);
            ldmatrix_x4(b1r[0], b1r[1], b1r[2], b1r[3], b_addr0 + 16 * PITCH_B + koff);
            mma_16816(d[0][0][0], d[0][0][1], d[0][0][2], d[0][0][3],
                      a0[0], a0[1], a0[2], a0[3], b0[0], b0[1]);
            mma_16816(d[0][1][0], d[0][1][1], d[0][1][2], d[0][1][3],
                      a0[0], a0[1], a0[2], a0[3], b0[2], b0[3]);
            mma_16816(d[0][2][0], d[0][2][1], d[0][2][2], d[0][2][3],
                      a0[0], a0[1], a0[2], a0[3], b1r[0], b1r[1]);
            mma_16816(d[0][3][0], d[0][3][1], d[0][3][2], d[0][3][3],
                      a0[0], a0[1], a0[2], a0[3], b1r[2], b1r[3]);
            mma_16816(d[1][0][0], d[1][0][1], d[1][0][2], d[1][0][3],
                      a1[0], a1[1], a1[2], a1[3], b0[0], b0[1]);
            mma_16816(d[1][1][0], d[1][1][1], d[1][1][2], d[1][1][3],
                      a1[0], a1[1], a1[2], a1[3], b0[2], b0[3]);
            mma_16816(d[1][2][0], d[1][2][1], d[1][2][2], d[1][2][3],
                      a1[0], a1[1], a1[2], a1[3], b1r[0], b1r[1]);
            mma_16816(d[1][3][0], d[1][3][1], d[1][3][2], d[1][3][3],
                      a1[0], a1[1], a1[2], a1[3], b1r[2], b1r[3]);
        }

        // ---- phase 3: epilogue relu(D + b1) * w2, reduce cols ----
        {
            float acc[2][2] = {{0.f, 0.f}, {0.f, 0.f}};
            #pragma unroll
            for (int nt = 0; nt < 4; nt++) {
                const int c0 = wn * 32 + nt * 8 + 2 * (lane & 3);
                const float bb0 = s->b1v[c0], bb1 = s->b1v[c0 + 1];
                const float ww0 = s->w2v[c0], ww1 = s->w2v[c0 + 1];
                #pragma unroll
                for (int mt = 0; mt < 2; mt++) {
                    acc[mt][0] += fmaxf(d[mt][nt][0] + bb0, 0.f) * ww0
                                + fmaxf(d[mt][nt][1] + bb1, 0.f) * ww1;
                    acc[mt][1] += fmaxf(d[mt][nt][2] + bb0, 0.f) * ww0
                                + fmaxf(d[mt][nt][3] + bb1, 0.f) * ww1;
                }
            }
            #pragma unroll
            for (int mt = 0; mt < 2; mt++) {
                #pragma unroll
                for (int i = 0; i < 2; i++) {
                    acc[mt][i] += __shfl_xor_sync(0xffffffffu, acc[mt][i], 1);
                    acc[mt][i] += __shfl_xor_sync(0xffffffffu, acc[mt][i], 2);
                }
            }
            if ((lane & 3) == 0) {
                const int row = wm * 32 + (lane >> 2);
                s->part[wn][row]      = acc[0][0];
                s->part[wn][row + 8]  = acc[0][1];
                s->part[wn][row + 16] = acc[1][0];
                s->part[wn][row + 24] = acc[1][1];
            }
        }
        __syncthreads();

        if (t < 128)
            s->scores[t] = (s->part[0][t] + s->part[1][t]) +
                           (s->part[2][t] + s->part[3][t]);
        __syncthreads();

        // ---- phase 4: masked exp weighting + prediction ----
        if (wid < 2) {
            const int tg = s->tgv[wid];
            float num = 0.f, den = 0.f;
            for (int hh = lane; hh < HIST; hh += 32) {
                int mm = wid * 64 + hh;
                float e = expf(s->scores[mm]);
                if (s->idxm[mm] == tg) e = 0.f;
                num += e * s->dots[mm];
                den += e;
            }
            #pragma unroll
            for (int o = 16; o; o >>= 1) {
                num += __shfl_xor_sync(0xffffffffu, num, o);
                den += __shfl_xor_sync(0xffffffffu, den, o);
            }
            if (lane == 0) {
                float pred = num / sqrtf(den);     // BETA = 0.5
                out[p * 2 + wid] = 1.f / (1.f + expf(-pred));
            }
        }
        __syncthreads();   // protect smem reuse for next pair
    }
}

// ---------------- launch ----------------
extern "C" void kernel_launch(void* const* d_in, const int* in_sizes, int n_in,
                              void* d_out, int out_size) {
    const int*   history = (const int*)  d_in[0];
    const int*   target  = (const int*)  d_in[1];
    const int*   near_p  = (const int*)  d_in[2];
    const float* E_in    = (const float*)d_in[4];
    const float* E_out   = (const float*)d_in[5];
    const float* E_hist  = (const float*)d_in[6];
    const float* E_targ  = (const float*)d_in[7];
    const float* W1      = (const float*)d_in[8];
    const float* b1      = (const float*)d_in[9];
    const float* W2      = (const float*)d_in[10];
    float* out = (float*)d_out;

    region_kernel<<<ITEM_NUM / 2, 128>>>(near_p, E_in, E_out);

    static int smem_set = 0;
    if (!smem_set) {
        cudaFuncSetAttribute(main_kernel,
                             cudaFuncAttributeMaxDynamicSharedMemorySize,
                             SMEM_TOTAL);
        smem_set = 1;
    }
    main_kernel<<<GRID_MAIN, TB, SMEM_TOTAL>>>(history, target, E_hist, E_targ,
                                               W1, b1, W2, out);
}

// round 5
// speedup vs baseline: 3.6761x; 1.2419x over previous
#include <cuda_runtime.h>
#include <cuda_bf16.h>
#include <cstdint>
#include <math.h>

#define ITEM_NUM 50000
#define BATCH    4096
#define HIST     50
#define KN       10
#define TB       512
#define GRID_MAIN 148

#define EPT      5                 // batch elements per tile (5 x 50 = 250 rows)
#define MROWS    256               // padded M tile
#define NTILE    ((BATCH + EPT - 1) / EPT)   // 820

// bf16 tile pitch: 264 bf16 = 528 B/row (132 words = 4 mod 32 banks ->
// ldmatrix 8-row phases hit distinct banks)
#define PITCH_B  528

// ---------------- device scratch (bf16 tables) ----------------
__device__ __nv_bfloat16 g_Ein_h  [ITEM_NUM * 64];
__device__ __nv_bfloat16 g_Eout_h [ITEM_NUM * 64];
__device__ __nv_bfloat16 g_Ehist_h[ITEM_NUM * 128];
__device__ __nv_bfloat16 g_rin_h  [ITEM_NUM * 64];
__device__ __nv_bfloat16 g_rout_h [ITEM_NUM * 64];

// ---------------- PTX helpers ----------------
__device__ __forceinline__ uint32_t smem_u32(const void* p) {
    uint32_t a;
    asm("{ .reg .u64 t; cvta.to.shared.u64 t, %1; cvt.u32.u64 %0, t; }" : "=r"(a) : "l"(p));
    return a;
}

__device__ __forceinline__ void ldmatrix_x4(uint32_t& r0, uint32_t& r1,
                                            uint32_t& r2, uint32_t& r3,
                                            uint32_t addr) {
    asm volatile("ldmatrix.sync.aligned.m8n8.x4.shared.b16 {%0,%1,%2,%3}, [%4];"
                 : "=r"(r0), "=r"(r1), "=r"(r2), "=r"(r3) : "r"(addr));
}

__device__ __forceinline__ void mma_16816(float& d0, float& d1, float& d2, float& d3,
                                          uint32_t a0, uint32_t a1, uint32_t a2, uint32_t a3,
                                          uint32_t b0, uint32_t b1) {
    asm volatile(
        "mma.sync.aligned.m16n8k16.row.col.f32.bf16.bf16.f32 "
        "{%0,%1,%2,%3}, {%4,%5,%6,%7}, {%8,%9}, {%0,%1,%2,%3};"
        : "+f"(d0), "+f"(d1), "+f"(d2), "+f"(d3)
        : "r"(a0), "r"(a1), "r"(a2), "r"(a3), "r"(b0), "r"(b1));
}

__device__ __forceinline__ uint2 f4_to_bf4(float4 a) {
    __nv_bfloat162 p0 = __floats2bfloat162_rn(a.x, a.y);
    __nv_bfloat162 p1 = __floats2bfloat162_rn(a.z, a.w);
    uint2 u;
    u.x = *reinterpret_cast<uint32_t*>(&p0);
    u.y = *reinterpret_cast<uint32_t*>(&p1);
    return u;
}

// multiply 8 bf16 (in uint4) by 8 fp32 targ values, accumulate fp32 dot,
// return bf16 products packed in uint4
__device__ __forceinline__ uint4 mul8(uint4 u, const float* tg, float& dot) {
    __nv_bfloat162* bp = reinterpret_cast<__nv_bfloat162*>(&u);
    uint4 o;
    uint32_t* op = reinterpret_cast<uint32_t*>(&o);
    #pragma unroll
    for (int i = 0; i < 4; i++) {
        float2 f = __bfloat1622float2(bp[i]);
        float x0 = f.x * tg[2 * i];
        float x1 = f.y * tg[2 * i + 1];
        dot += x0 + x1;
        __nv_bfloat162 pb = __floats2bfloat162_rn(x0, x1);
        op[i] = *reinterpret_cast<uint32_t*>(&pb);
    }
    return o;
}

// ---------------- kernel 0: fp32 tables -> bf16 ----------------
__global__ void conv_kernel(const float* __restrict__ E_in,
                            const float* __restrict__ E_out,
                            const float* __restrict__ E_hist) {
    int i = blockIdx.x * blockDim.x + threadIdx.x;
    int stride = gridDim.x * blockDim.x;
    const float4* in4  = reinterpret_cast<const float4*>(E_in);
    const float4* out4 = reinterpret_cast<const float4*>(E_out);
    const float4* hi4  = reinterpret_cast<const float4*>(E_hist);
    uint2* din  = reinterpret_cast<uint2*>(g_Ein_h);
    uint2* dout = reinterpret_cast<uint2*>(g_Eout_h);
    uint2* dhi  = reinterpret_cast<uint2*>(g_Ehist_h);
    for (int v = i; v < ITEM_NUM * 64 / 4; v += stride) {
        din [v] = f4_to_bf4(in4 [v]);
        dout[v] = f4_to_bf4(out4[v]);
    }
    for (int v = i; v < ITEM_NUM * 128 / 4; v += stride)
        dhi[v] = f4_to_bf4(hi4[v]);
}

// ---------------- kernel A: region self-attention (bf16 I/O) -------------
__global__ void region_kernel(const int* __restrict__ near_pois) {
    __shared__ float in_s [2][640];
    __shared__ float out_s[2][640];
    __shared__ float wo_s [2][10];
    __shared__ float wi_s [2][10];
    __shared__ int   idx_s[2][10];

    int li = threadIdx.x >> 6;
    int d  = threadIdx.x & 63;
    int n  = blockIdx.x * 2 + li;

    if (d < KN) idx_s[li][d] = near_pois[n * KN + d];
    __syncthreads();

    #pragma unroll
    for (int k = 0; k < KN; k++) {
        int idx = idx_s[li][k];
        in_s [li][k * 64 + d] = __bfloat162float(g_Ein_h [idx * 64 + d]);
        out_s[li][k * 64 + d] = __bfloat162float(g_Eout_h[idx * 64 + d]);
    }
    __syncthreads();

    if (d < KN) {
        float s = 0.f;
        #pragma unroll
        for (int i = 0; i < 64; i++) s += in_s[li][i] * out_s[li][i * KN + d];
        wo_s[li][d] = expf(s * 0.125f);
    } else if (d >= 32 && d < 32 + KN) {
        int k = d - 32;
        float s = 0.f;
        #pragma unroll
        for (int i = 0; i < 64; i++) s += out_s[li][i] * in_s[li][i * KN + k];
        wi_s[li][k] = expf(s * 0.125f);
    }
    __syncthreads();

    float so = 0.f, si = 0.f;
    #pragma unroll
    for (int k = 0; k < KN; k++) { so += wo_s[li][k]; si += wi_s[li][k]; }
    float ro = 0.f, ri = 0.f;
    #pragma unroll
    for (int k = 0; k < KN; k++) {
        ro += wo_s[li][k] * out_s[li][k * 64 + d];
        ri += wi_s[li][k] * in_s [li][k * 64 + d];
    }
    g_rout_h[n * 64 + d] = __float2bfloat16(ro / so);
    g_rin_h [n * 64 + d] = __float2bfloat16(ri / si);
}

// ---------------- main kernel: 256-row warp-MMA tiles ---------------------
// smem: X bf16 [256][PITCH], W bf16 [128][PITCH], Aux
#define SM_X   0
#define SM_W   (MROWS * PITCH_B)                 // 135168
#define SM_AUX (SM_W + 128 * PITCH_B)            // 202752

struct Aux {
    float targ[EPT][256];
    float b1v[128];
    float w2v[128];
    float part[4][MROWS];
    float dots[MROWS];
    int   idxm[MROWS];
    int   tgv[EPT];
    float scores[MROWS];
};
#define SMEM_TOTAL (SM_AUX + (int)sizeof(Aux))

__global__ __launch_bounds__(TB, 1)
void main_kernel(const int*   __restrict__ history,
                 const int*   __restrict__ target,
                 const float* __restrict__ E_targ,
                 const float* __restrict__ W1,
                 const float* __restrict__ b1,
                 const float* __restrict__ W2,
                 float*       __restrict__ out) {
    extern __shared__ char sm[];
    Aux* s = reinterpret_cast<Aux*>(sm + SM_AUX);
    const uint32_t sbase = smem_u32(sm);

    const int t    = threadIdx.x;
    const int wid  = t >> 5;
    const int lane = t & 31;

    // gather mapping: m = row (0..255), hhalf = which 128-element half
    const int m     = t >> 1;
    const int hhalf = t & 1;
    const int relem = m / 50;             // element slot within tile (0..4 for valid)
    const int hrow  = m - relem * 50;

    const int wm = wid & 3;   // warp m-tile: rows wm*64 .. +64
    const int wn = wid >> 2;  // warp n-tile: cols wn*32 .. +32

    // ---- prologue ----
    {   // zero X (pad rows 250..255 stay zero forever)
        uint4 z = make_uint4(0, 0, 0, 0);
        for (int i = t; i < MROWS * PITCH_B / 16; i += TB)
            reinterpret_cast<uint4*>(sm + SM_X)[i] = z;
    }
    {   // W1 -> bf16 smem (row j = t>>2, quarter t&3)
        const int jm = t >> 2, jq = t & 3;
        const float4* src4 = reinterpret_cast<const float4*>(W1 + jm * 256 + jq * 64);
        char* dst = sm + SM_W + jm * PITCH_B + jq * 128;
        #pragma unroll
        for (int g = 0; g < 8; g++) {
            float4 a = src4[g * 2], b = src4[g * 2 + 1];
            uint2 u0 = f4_to_bf4(a), u1 = f4_to_bf4(b);
            uint4 u;
            u.x = u0.x; u.y = u0.y; u.z = u1.x; u.w = u1.y;
            *reinterpret_cast<uint4*>(dst + g * 16) = u;
        }
    }
    if (t < 128) { s->b1v[t] = b1[t]; s->w2v[t] = W2[t]; }
    __syncthreads();

    // ldmatrix addresses
    const int a_row0 = wm * 64 + ((lane >> 3) & 1) * 8 + (lane & 7);
    const uint32_t a_addr0 = sbase + SM_X + a_row0 * PITCH_B + (lane >> 4) * 16;
    const int b_row = wn * 32 + (lane >> 4) * 8 + (lane & 7);
    const uint32_t b_addr0 = sbase + SM_W + b_row * PITCH_B + ((lane >> 3) & 1) * 16;

    for (int p = blockIdx.x; p < NTILE; p += gridDim.x) {
        const bool rowvalid = (m < EPT * HIST) && (p * EPT + relem < BATCH);

        // ---- phase 0: targets + targ vectors ----
        if (t < EPT) {
            int e = p * EPT + t;
            s->tgv[t] = target[e < BATCH ? e : (BATCH - 1)];
        }
        for (int v = t; v < EPT * 256; v += TB) {
            int rr = v >> 8, e = v & 255;
            int be = p * EPT + rr;
            int tg = target[be < BATCH ? be : (BATCH - 1)];
            float val;
            if (e < 128)      val = E_targ[tg * 128 + e];
            else if (e < 192) val = __bfloat162float(g_rout_h[tg * 64 + (e - 128)]);
            else              val = __bfloat162float(g_rin_h [tg * 64 + (e - 192)]);
            s->targ[rr][e] = val;
        }
        int idx = 0;
        if (hhalf == 0 && rowvalid)
            idx = history[(p * EPT + relem) * HIST + hrow];
        idx = __shfl_sync(0xffffffffu, idx, lane & ~1);
        if (hhalf == 0 && rowvalid) s->idxm[m] = idx;
        __syncthreads();

        // ---- phase 1: gather bf16, x = hist*targ, fp32 dots ----
        float dot = 0.f;
        if (rowvalid) {
            const float* tgp = &s->targ[relem][hhalf * 128];
            char* dst = sm + SM_X + m * PITCH_B + hhalf * 256;
            if (hhalf == 0) {
                const uint4* src = reinterpret_cast<const uint4*>(g_Ehist_h + idx * 128);
                #pragma unroll
                for (int g = 0; g < 16; g++)
                    *reinterpret_cast<uint4*>(dst + g * 16) = mul8(src[g], tgp + g * 8, dot);
            } else {
                const uint4* s0 = reinterpret_cast<const uint4*>(g_rin_h  + idx * 64);
                const uint4* s1 = reinterpret_cast<const uint4*>(g_rout_h + idx * 64);
                #pragma unroll
                for (int g = 0; g < 8; g++)
                    *reinterpret_cast<uint4*>(dst + g * 16) = mul8(s0[g], tgp + g * 8, dot);
                #pragma unroll
                for (int g = 0; g < 8; g++)
                    *reinterpret_cast<uint4*>(dst + 128 + g * 16) =
                        mul8(s1[g], tgp + 64 + g * 8, dot);
            }
        }
        dot += __shfl_xor_sync(0xffffffffu, dot, 1);
        if (hhalf == 0 && rowvalid) s->dots[m] = dot;
        __syncthreads();

        // ---- phase 2: warp MMA 64x32 tile, D in registers ----
        float d[4][4][4];
        #pragma unroll
        for (int mf = 0; mf < 4; mf++)
            #pragma unroll
            for (int nf = 0; nf < 4; nf++)
                #pragma unroll
                for (int i = 0; i < 4; i++) d[mf][nf][i] = 0.f;

        #pragma unroll
        for (int ks = 0; ks < 16; ks++) {
            const uint32_t koff = ks * 32;
            uint32_t b0[4], b1r[4];
            ldmatrix_x4(b0[0], b0[1], b0[2], b0[3], b_addr0 + koff);
            ldmatrix_x4(b1r[0], b1r[1], b1r[2], b1r[3], b_addr0 + 16 * PITCH_B + koff);
            #pragma unroll
            for (int mf = 0; mf < 4; mf++) {
                uint32_t a[4];
                ldmatrix_x4(a[0], a[1], a[2], a[3],
                            a_addr0 + mf * 16 * PITCH_B + koff);
                mma_16816(d[mf][0][0], d[mf][0][1], d[mf][0][2], d[mf][0][3],
                          a[0], a[1], a[2], a[3], b0[0], b0[1]);
                mma_16816(d[mf][1][0], d[mf][1][1], d[mf][1][2], d[mf][1][3],
                          a[0], a[1], a[2], a[3], b0[2], b0[3]);
                mma_16816(d[mf][2][0], d[mf][2][1], d[mf][2][2], d[mf][2][3],
                          a[0], a[1], a[2], a[3], b1r[0], b1r[1]);
                mma_16816(d[mf][3][0], d[mf][3][1], d[mf][3][2], d[mf][3][3],
                          a[0], a[1], a[2], a[3], b1r[2], b1r[3]);
            }
        }

        // ---- phase 3: epilogue relu(D + b1) * w2, reduce cols ----
        {
            float acc[4][2];
            #pragma unroll
            for (int mf = 0; mf < 4; mf++) { acc[mf][0] = 0.f; acc[mf][1] = 0.f; }
            #pragma unroll
            for (int nf = 0; nf < 4; nf++) {
                const int c0 = wn * 32 + nf * 8 + 2 * (lane & 3);
                const float bb0 = s->b1v[c0], bb1 = s->b1v[c0 + 1];
                const float ww0 = s->w2v[c0], ww1 = s->w2v[c0 + 1];
                #pragma unroll
                for (int mf = 0; mf < 4; mf++) {
                    acc[mf][0] += fmaxf(d[mf][nf][0] + bb0, 0.f) * ww0
                                + fmaxf(d[mf][nf][1] + bb1, 0.f) * ww1;
                    acc[mf][1] += fmaxf(d[mf][nf][2] + bb0, 0.f) * ww0
                                + fmaxf(d[mf][nf][3] + bb1, 0.f) * ww1;
                }
            }
            #pragma unroll
            for (int mf = 0; mf < 4; mf++) {
                #pragma unroll
                for (int i = 0; i < 2; i++) {
                    acc[mf][i] += __shfl_xor_sync(0xffffffffu, acc[mf][i], 1);
                    acc[mf][i] += __shfl_xor_sync(0xffffffffu, acc[mf][i], 2);
                }
            }
            if ((lane & 3) == 0) {
                #pragma unroll
                for (int mf = 0; mf < 4; mf++) {
                    const int row = wm * 64 + mf * 16 + (lane >> 2);
                    s->part[wn][row]     = acc[mf][0];
                    s->part[wn][row + 8] = acc[mf][1];
                }
            }
        }
        __syncthreads();

        if (t < MROWS)
            s->scores[t] = (s->part[0][t] + s->part[1][t]) +
                           (s->part[2][t] + s->part[3][t]);
        __syncthreads();

        // ---- phase 4: masked exp weighting + prediction (warp per elem) ----
        if (wid < EPT && (p * EPT + wid) < BATCH) {
            const int tg = s->tgv[wid];
            float num = 0.f, den = 0.f;
            #pragma unroll
            for (int it = 0; it < 2; it++) {
                int hh = lane + it * 32;
                if (hh < HIST) {
                    int mm = wid * HIST + hh;
                    float e = expf(s->scores[mm]);
                    if (s->idxm[mm] == tg) e = 0.f;
                    num += e * s->dots[mm];
                    den += e;
                }
            }
            #pragma unroll
            for (int o = 16; o; o >>= 1) {
                num += __shfl_xor_sync(0xffffffffu, num, o);
                den += __shfl_xor_sync(0xffffffffu, den, o);
            }
            if (lane == 0) {
                float pred = num / sqrtf(den);     // BETA = 0.5
                out[p * EPT + wid] = 1.f / (1.f + expf(-pred));
            }
        }
        __syncthreads();   // protect smem reuse for next tile
    }
}

// ---------------- launch ----------------
extern "C" void kernel_launch(void* const* d_in, const int* in_sizes, int n_in,
                              void* d_out, int out_size) {
    const int*   history = (const int*)  d_in[0];
    const int*   target  = (const int*)  d_in[1];
    const int*   near_p  = (const int*)  d_in[2];
    const float* E_in    = (const float*)d_in[4];
    const float* E_out   = (const float*)d_in[5];
    const float* E_hist  = (const float*)d_in[6];
    const float* E_targ  = (const float*)d_in[7];
    const float* W1      = (const float*)d_in[8];
    const float* b1      = (const float*)d_in[9];
    const float* W2      = (const float*)d_in[10];
    float* out = (float*)d_out;

    conv_kernel<<<512, 256>>>(E_in, E_out, E_hist);
    region_kernel<<<ITEM_NUM / 2, 128>>>(near_p);

    cudaFuncSetAttribute(main_kernel,
                         cudaFuncAttributeMaxDynamicSharedMemorySize,
                         SMEM_TOTAL);
    main_kernel<<<GRID_MAIN, TB, SMEM_TOTAL>>>(history, target, E_targ,
                                               W1, b1, W2, out);
}

// round 6
// speedup vs baseline: 3.8847x; 1.0567x over previous
#include <cuda_runtime.h>
#include <cuda_bf16.h>
#include <cstdint>
#include <math.h>

#define ITEM_NUM 50000
#define BATCH    4096
#define HIST     50
#define KN       10
#define TB       512
#define GRID_MAIN 148

#define EPT      5                 // batch elements per tile (5 x 50 = 250 rows)
#define MROWS    256               // padded M tile
#define NTILE    ((BATCH + EPT - 1) / EPT)   // 820

// fp8 tile pitch: 272 B/row (68 words = 4 mod 32 banks -> ldmatrix 8-row
// phases hit distinct bank groups)
#define PITCH_F  272

#define SCALE_X  4096.0f           // 2^12
#define SCALE_W  256.0f            // 2^8
#define INV_SCALE 9.5367431640625e-7f   // 2^-20

// ---------------- device scratch (bf16 tables) ----------------
__device__ __nv_bfloat16 g_Ein_h  [ITEM_NUM * 64];
__device__ __nv_bfloat16 g_Eout_h [ITEM_NUM * 64];
__device__ __nv_bfloat16 g_Ehist_h[ITEM_NUM * 128];
__device__ __nv_bfloat16 g_rin_h  [ITEM_NUM * 64];
__device__ __nv_bfloat16 g_rout_h [ITEM_NUM * 64];

// ---------------- PTX helpers ----------------
__device__ __forceinline__ uint32_t smem_u32(const void* p) {
    uint32_t a;
    asm("{ .reg .u64 t; cvta.to.shared.u64 t, %1; cvt.u32.u64 %0, t; }" : "=r"(a) : "l"(p));
    return a;
}

__device__ __forceinline__ void ldmatrix_x4(uint32_t& r0, uint32_t& r1,
                                            uint32_t& r2, uint32_t& r3,
                                            uint32_t addr) {
    asm volatile("ldmatrix.sync.aligned.m8n8.x4.shared.b16 {%0,%1,%2,%3}, [%4];"
                 : "=r"(r0), "=r"(r1), "=r"(r2), "=r"(r3) : "r"(addr));
}

// fp8 e4m3 MMA, K=32
__device__ __forceinline__ void mma_fp8(float& d0, float& d1, float& d2, float& d3,
                                        uint32_t a0, uint32_t a1, uint32_t a2, uint32_t a3,
                                        uint32_t b0, uint32_t b1) {
    asm volatile(
        "mma.sync.aligned.m16n8k32.row.col.f32.e4m3.e4m3.f32 "
        "{%0,%1,%2,%3}, {%4,%5,%6,%7}, {%8,%9}, {%0,%1,%2,%3};"
        : "+f"(d0), "+f"(d1), "+f"(d2), "+f"(d3)
        : "r"(a0), "r"(a1), "r"(a2), "r"(a3), "r"(b0), "r"(b1));
}

// pack 4 floats -> 4 e4m3 bytes (byte0 = f0)
__device__ __forceinline__ uint32_t pack4_e4m3(float f0, float f1, float f2, float f3) {
    uint16_t lo, hi;
    asm("cvt.rn.satfinite.e4m3x2.f32 %0, %1, %2;" : "=h"(lo) : "f"(f1), "f"(f0));
    asm("cvt.rn.satfinite.e4m3x2.f32 %0, %1, %2;" : "=h"(hi) : "f"(f3), "f"(f2));
    return (uint32_t)lo | ((uint32_t)hi << 16);
}

__device__ __forceinline__ uint2 f4_to_bf4(float4 a) {
    __nv_bfloat162 p0 = __floats2bfloat162_rn(a.x, a.y);
    __nv_bfloat162 p1 = __floats2bfloat162_rn(a.z, a.w);
    uint2 u;
    u.x = *reinterpret_cast<uint32_t*>(&p0);
    u.y = *reinterpret_cast<uint32_t*>(&p1);
    return u;
}

// 16 bf16 (two uint4) * 16 fp32 targ -> fp8x16 (uint4), accumulate fp32 dot
__device__ __forceinline__ void mul16_store(uint4 u0, uint4 u1, const float* tg,
                                            float& dot, void* dst) {
    float x[16];
    const __nv_bfloat162* b0 = reinterpret_cast<const __nv_bfloat162*>(&u0);
    const __nv_bfloat162* b1 = reinterpret_cast<const __nv_bfloat162*>(&u1);
    #pragma unroll
    for (int i = 0; i < 4; i++) {
        float2 f = __bfloat1622float2(b0[i]);
        x[2 * i]     = f.x * tg[2 * i];
        x[2 * i + 1] = f.y * tg[2 * i + 1];
    }
    #pragma unroll
    for (int i = 0; i < 4; i++) {
        float2 f = __bfloat1622float2(b1[i]);
        x[8 + 2 * i]     = f.x * tg[8 + 2 * i];
        x[8 + 2 * i + 1] = f.y * tg[8 + 2 * i + 1];
    }
    #pragma unroll
    for (int i = 0; i < 16; i++) dot += x[i];
    uint4 o;
    o.x = pack4_e4m3(x[0] * SCALE_X,  x[1] * SCALE_X,  x[2] * SCALE_X,  x[3] * SCALE_X);
    o.y = pack4_e4m3(x[4] * SCALE_X,  x[5] * SCALE_X,  x[6] * SCALE_X,  x[7] * SCALE_X);
    o.z = pack4_e4m3(x[8] * SCALE_X,  x[9] * SCALE_X,  x[10] * SCALE_X, x[11] * SCALE_X);
    o.w = pack4_e4m3(x[12] * SCALE_X, x[13] * SCALE_X, x[14] * SCALE_X, x[15] * SCALE_X);
    *reinterpret_cast<uint4*>(dst) = o;
}

// ---------------- kernel 0: fp32 tables -> bf16 ----------------
__global__ void conv_kernel(const float* __restrict__ E_in,
                            const float* __restrict__ E_out,
                            const float* __restrict__ E_hist) {
    int i = blockIdx.x * blockDim.x + threadIdx.x;
    int stride = gridDim.x * blockDim.x;
    const float4* in4  = reinterpret_cast<const float4*>(E_in);
    const float4* out4 = reinterpret_cast<const float4*>(E_out);
    const float4* hi4  = reinterpret_cast<const float4*>(E_hist);
    uint2* din  = reinterpret_cast<uint2*>(g_Ein_h);
    uint2* dout = reinterpret_cast<uint2*>(g_Eout_h);
    uint2* dhi  = reinterpret_cast<uint2*>(g_Ehist_h);
    for (int v = i; v < ITEM_NUM * 64 / 4; v += stride) {
        din [v] = f4_to_bf4(in4 [v]);
        dout[v] = f4_to_bf4(out4[v]);
    }
    for (int v = i; v < ITEM_NUM * 128 / 4; v += stride)
        dhi[v] = f4_to_bf4(hi4[v]);
}

// ---------------- kernel A: region self-attention (vector gather) --------
__global__ void region_kernel(const int* __restrict__ near_pois) {
    __shared__ float in_s [2][640];
    __shared__ float out_s[2][640];
    __shared__ float wo_s [2][10];
    __shared__ float wi_s [2][10];
    __shared__ int   idx_s[2][10];

    int t  = threadIdx.x;
    int li = t >> 6;
    int d  = t & 63;
    int n  = blockIdx.x * 2 + li;

    if (d < KN) idx_s[li][d] = near_pois[n * KN + d];
    __syncthreads();

    // vectorized gather: 320 uint4 per block (2 items x 2 tables x 10 rows x 8)
    for (int v = t; v < 320; v += 128) {
        int li2 = (v >= 160) ? 1 : 0;
        int r0  = v - li2 * 160;
        int tb  = (r0 >= 80) ? 1 : 0;
        int rr  = r0 - tb * 80;
        int k   = rr >> 3, c = rr & 7;
        int idx = idx_s[li2][k];
        const uint4* src = reinterpret_cast<const uint4*>(
            (tb ? g_Eout_h : g_Ein_h) + idx * 64);
        uint4 u = src[c];
        float* dstp = (tb ? out_s[li2] : in_s[li2]) + k * 64 + c * 8;
        const __nv_bfloat162* bp = reinterpret_cast<const __nv_bfloat162*>(&u);
        #pragma unroll
        for (int i = 0; i < 4; i++) {
            float2 f = __bfloat1622float2(bp[i]);
            dstp[2 * i]     = f.x;
            dstp[2 * i + 1] = f.y;
        }
    }
    __syncthreads();

    if (d < KN) {
        float s = 0.f;
        #pragma unroll
        for (int i = 0; i < 64; i++) s += in_s[li][i] * out_s[li][i * KN + d];
        wo_s[li][d] = expf(s * 0.125f);
    } else if (d >= 32 && d < 32 + KN) {
        int k = d - 32;
        float s = 0.f;
        #pragma unroll
        for (int i = 0; i < 64; i++) s += out_s[li][i] * in_s[li][i * KN + k];
        wi_s[li][k] = expf(s * 0.125f);
    }
    __syncthreads();

    float so = 0.f, si = 0.f;
    #pragma unroll
    for (int k = 0; k < KN; k++) { so += wo_s[li][k]; si += wi_s[li][k]; }
    float ro = 0.f, ri = 0.f;
    #pragma unroll
    for (int k = 0; k < KN; k++) {
        ro += wo_s[li][k] * out_s[li][k * 64 + d];
        ri += wi_s[li][k] * in_s [li][k * 64 + d];
    }
    g_rout_h[n * 64 + d] = __float2bfloat16(ro / so);
    g_rin_h [n * 64 + d] = __float2bfloat16(ri / si);
}

// ---------------- main kernel: 256-row fp8 warp-MMA tiles -----------------
// smem: X fp8 [256][PITCH_F], W fp8 [128][PITCH_F], Aux
#define SM_X   0
#define SM_W   (MROWS * PITCH_F)                 // 69632
#define SM_AUX (SM_W + 128 * PITCH_F)            // 104448

struct Aux {
    float targ[EPT][256];
    float b1v[128];
    float w2v[128];
    float part[4][MROWS];
    float dots[MROWS];
    int   idxm[MROWS];
    int   tgv[EPT];
    float scores[MROWS];
};
#define SMEM_TOTAL (SM_AUX + (int)sizeof(Aux))

__global__ __launch_bounds__(TB, 1)
void main_kernel(const int*   __restrict__ history,
                 const int*   __restrict__ target,
                 const float* __restrict__ E_targ,
                 const float* __restrict__ W1,
                 const float* __restrict__ b1,
                 const float* __restrict__ W2,
                 float*       __restrict__ out) {
    extern __shared__ char sm[];
    Aux* s = reinterpret_cast<Aux*>(sm + SM_AUX);
    const uint32_t sbase = smem_u32(sm);

    const int t    = threadIdx.x;
    const int wid  = t >> 5;
    const int lane = t & 31;

    const int m     = t >> 1;             // gather row (0..255)
    const int hhalf = t & 1;              // which 128-element half
    const int relem = m / 50;
    const int hrow  = m - relem * 50;

    const int wm = wid & 3;   // warp m-tile: rows wm*64 .. +64
    const int wn = wid >> 2;  // warp n-tile: cols wn*32 .. +32

    // ---- prologue ----
    {   // zero X (pad rows 250..255 stay zero forever)
        uint4 z = make_uint4(0, 0, 0, 0);
        for (int i = t; i < MROWS * PITCH_F / 16; i += TB)
            reinterpret_cast<uint4*>(sm + SM_X)[i] = z;
    }
    {   // W1 -> fp8 smem (row j = t>>2, 64-col quarter t&3), scaled by 2^8
        const int jm = t >> 2, jq = t & 3;
        const float4* src4 = reinterpret_cast<const float4*>(W1 + jm * 256 + jq * 64);
        char* dst = sm + SM_W + jm * PITCH_F + jq * 64;
        #pragma unroll
        for (int g = 0; g < 4; g++) {
            float4 a = src4[g * 4], b = src4[g * 4 + 1];
            float4 c = src4[g * 4 + 2], e = src4[g * 4 + 3];
            uint4 u;
            u.x = pack4_e4m3(a.x * SCALE_W, a.y * SCALE_W, a.z * SCALE_W, a.w * SCALE_W);
            u.y = pack4_e4m3(b.x * SCALE_W, b.y * SCALE_W, b.z * SCALE_W, b.w * SCALE_W);
            u.z = pack4_e4m3(c.x * SCALE_W, c.y * SCALE_W, c.z * SCALE_W, c.w * SCALE_W);
            u.w = pack4_e4m3(e.x * SCALE_W, e.y * SCALE_W, e.z * SCALE_W, e.w * SCALE_W);
            *reinterpret_cast<uint4*>(dst + g * 16) = u;
        }
    }
    if (t < 128) { s->b1v[t] = b1[t]; s->w2v[t] = W2[t]; }
    __syncthreads();

    // ldmatrix addresses (fp8: 16B chunk = 16 cols; k-step stride = 32 B)
    const int a_row0 = wm * 64 + ((lane >> 3) & 1) * 8 + (lane & 7);
    const uint32_t a_addr0 = sbase + SM_X + a_row0 * PITCH_F + (lane >> 4) * 16;
    const int b_row = wn * 32 + (lane >> 4) * 8 + (lane & 7);
    const uint32_t b_addr0 = sbase + SM_W + b_row * PITCH_F + ((lane >> 3) & 1) * 16;

    for (int p = blockIdx.x; p < NTILE; p += gridDim.x) {
        const bool rowvalid = (m < EPT * HIST) && (p * EPT + relem < BATCH);

        // ---- phase 0: targets + targ vectors ----
        if (t < EPT) {
            int e = p * EPT + t;
            s->tgv[t] = target[e < BATCH ? e : (BATCH - 1)];
        }
        for (int v = t; v < EPT * 256; v += TB) {
            int rr = v >> 8, e = v & 255;
            int be = p * EPT + rr;
            int tg = target[be < BATCH ? be : (BATCH - 1)];
            float val;
            if (e < 128)      val = E_targ[tg * 128 + e];
            else if (e < 192) val = __bfloat162float(g_rout_h[tg * 64 + (e - 128)]);
            else              val = __bfloat162float(g_rin_h [tg * 64 + (e - 192)]);
            s->targ[rr][e] = val;
        }
        int idx = 0;
        if (hhalf == 0 && rowvalid)
            idx = history[(p * EPT + relem) * HIST + hrow];
        idx = __shfl_sync(0xffffffffu, idx, lane & ~1);
        if (hhalf == 0 && rowvalid) s->idxm[m] = idx;
        __syncthreads();

        // ---- phase 1: gather bf16, x = hist*targ -> fp8 smem; fp32 dots ----
        float dot = 0.f;
        if (rowvalid) {
            const float* tgp = &s->targ[relem][hhalf * 128];
            char* dst = sm + SM_X + m * PITCH_F + hhalf * 128;
            if (hhalf == 0) {
                const uint4* src = reinterpret_cast<const uint4*>(g_Ehist_h + idx * 128);
                #pragma unroll
                for (int g = 0; g < 8; g++)
                    mul16_store(src[2 * g], src[2 * g + 1], tgp + 16 * g, dot,
                                dst + 16 * g);
            } else {
                const uint4* s0 = reinterpret_cast<const uint4*>(g_rin_h  + idx * 64);
                const uint4* s1 = reinterpret_cast<const uint4*>(g_rout_h + idx * 64);
                #pragma unroll
                for (int g = 0; g < 4; g++)
                    mul16_store(s0[2 * g], s0[2 * g + 1], tgp + 16 * g, dot,
                                dst + 16 * g);
                #pragma unroll
                for (int g = 0; g < 4; g++)
                    mul16_store(s1[2 * g], s1[2 * g + 1], tgp + 64 + 16 * g, dot,
                                dst + 64 + 16 * g);
            }
        }
        dot += __shfl_xor_sync(0xffffffffu, dot, 1);
        if (hhalf == 0 && rowvalid) s->dots[m] = dot;
        __syncthreads();

        // ---- phase 2: warp MMA 64x32 fp8 tile, D in registers ----
        float d[4][4][4];
        #pragma unroll
        for (int mf = 0; mf < 4; mf++)
            #pragma unroll
            for (int nf = 0; nf < 4; nf++)
                #pragma unroll
                for (int i = 0; i < 4; i++) d[mf][nf][i] = 0.f;

        #pragma unroll
        for (int ks = 0; ks < 8; ks++) {
            const uint32_t koff = ks * 32;
            uint32_t b0[4], b1r[4];
            ldmatrix_x4(b0[0], b0[1], b0[2], b0[3], b_addr0 + koff);
            ldmatrix_x4(b1r[0], b1r[1], b1r[2], b1r[3],
                        b_addr0 + 16 * PITCH_F + koff);
            #pragma unroll
            for (int mf = 0; mf < 4; mf++) {
                uint32_t a[4];
                ldmatrix_x4(a[0], a[1], a[2], a[3],
                            a_addr0 + mf * 16 * PITCH_F + koff);
                mma_fp8(d[mf][0][0], d[mf][0][1], d[mf][0][2], d[mf][0][3],
                        a[0], a[1], a[2], a[3], b0[0], b0[1]);
                mma_fp8(d[mf][1][0], d[mf][1][1], d[mf][1][2], d[mf][1][3],
                        a[0], a[1], a[2], a[3], b0[2], b0[3]);
                mma_fp8(d[mf][2][0], d[mf][2][1], d[mf][2][2], d[mf][2][3],
                        a[0], a[1], a[2], a[3], b1r[0], b1r[1]);
                mma_fp8(d[mf][3][0], d[mf][3][1], d[mf][3][2], d[mf][3][3],
                        a[0], a[1], a[2], a[3], b1r[2], b1r[3]);
            }
        }

        // ---- phase 3: epilogue relu(D*2^-20 + b1) * w2, reduce cols ----
        {
            float acc[4][2];
            #pragma unroll
            for (int mf = 0; mf < 4; mf++) { acc[mf][0] = 0.f; acc[mf][1] = 0.f; }
            #pragma unroll
            for (int nf = 0; nf < 4; nf++) {
                const int c0 = wn * 32 + nf * 8 + 2 * (lane & 3);
                const float bb0 = s->b1v[c0], bb1 = s->b1v[c0 + 1];
                const float ww0 = s->w2v[c0], ww1 = s->w2v[c0 + 1];
                #pragma unroll
                for (int mf = 0; mf < 4; mf++) {
                    acc[mf][0] += fmaxf(fmaf(d[mf][nf][0], INV_SCALE, bb0), 0.f) * ww0
                                + fmaxf(fmaf(d[mf][nf][1], INV_SCALE, bb1), 0.f) * ww1;
                    acc[mf][1] += fmaxf(fmaf(d[mf][nf][2], INV_SCALE, bb0), 0.f) * ww0
                                + fmaxf(fmaf(d[mf][nf][3], INV_SCALE, bb1), 0.f) * ww1;
                }
            }
            #pragma unroll
            for (int mf = 0; mf < 4; mf++) {
                #pragma unroll
                for (int i = 0; i < 2; i++) {
                    acc[mf][i] += __shfl_xor_sync(0xffffffffu, acc[mf][i], 1);
                    acc[mf][i] += __shfl_xor_sync(0xffffffffu, acc[mf][i], 2);
                }
            }
            if ((lane & 3) == 0) {
                #pragma unroll
                for (int mf = 0; mf < 4; mf++) {
                    const int row = wm * 64 + mf * 16 + (lane >> 2);
                    s->part[wn][row]     = acc[mf][0];
                    s->part[wn][row + 8] = acc[mf][1];
                }
            }
        }
        __syncthreads();

        if (t < MROWS)
            s->scores[t] = (s->part[0][t] + s->part[1][t]) +
                           (s->part[2][t] + s->part[3][t]);
        __syncthreads();

        // ---- phase 4: masked exp weighting + prediction (warp per elem) ----
        if (wid < EPT && (p * EPT + wid) < BATCH) {
            const int tg = s->tgv[wid];
            float num = 0.f, den = 0.f;
            #pragma unroll
            for (int it = 0; it < 2; it++) {
                int hh = lane + it * 32;
                if (hh < HIST) {
                    int mm = wid * HIST + hh;
                    float e = expf(s->scores[mm]);
                    if (s->idxm[mm] == tg) e = 0.f;
                    num += e * s->dots[mm];
                    den += e;
                }
            }
            #pragma unroll
            for (int o = 16; o; o >>= 1) {
                num += __shfl_xor_sync(0xffffffffu, num, o);
                den += __shfl_xor_sync(0xffffffffu, den, o);
            }
            if (lane == 0) {
                float pred = num / sqrtf(den);     // BETA = 0.5
                out[p * EPT + wid] = 1.f / (1.f + expf(-pred));
            }
        }
        __syncthreads();   // protect smem reuse for next tile
    }
}

// ---------------- launch ----------------
extern "C" void kernel_launch(void* const* d_in, const int* in_sizes, int n_in,
                              void* d_out, int out_size) {
    const int*   history = (const int*)  d_in[0];
    const int*   target  = (const int*)  d_in[1];
    const int*   near_p  = (const int*)  d_in[2];
    const float* E_in    = (const float*)d_in[4];
    const float* E_out   = (const float*)d_in[5];
    const float* E_hist  = (const float*)d_in[6];
    const float* E_targ  = (const float*)d_in[7];
    const float* W1      = (const float*)d_in[8];
    const float* b1      = (const float*)d_in[9];
    const float* W2      = (const float*)d_in[10];
    float* out = (float*)d_out;

    conv_kernel<<<512, 256>>>(E_in, E_out, E_hist);
    region_kernel<<<ITEM_NUM / 2, 128>>>(near_p);

    cudaFuncSetAttribute(main_kernel,
                         cudaFuncAttributeMaxDynamicSharedMemorySize,
                         SMEM_TOTAL);
    main_kernel<<<GRID_MAIN, TB, SMEM_TOTAL>>>(history, target, E_targ,
                                               W1, b1, W2, out);
}

// round 7
// speedup vs baseline: 3.9661x; 1.0209x over previous
#include <cuda_runtime.h>
#include <cuda_bf16.h>
#include <cstdint>
#include <math.h>

#define ITEM_NUM 50000
#define BATCH    4096
#define HIST     50
#define KN       10
#define TB       512
#define GRID_MAIN 148

#define EPT      5                 // batch elements per tile (5 x 50 = 250 rows)
#define MROWS    256               // padded M tile
#define NTILE    ((BATCH + EPT - 1) / EPT)   // 820

// fp8 tile pitch: 272 B/row
#define PITCH_F  272

#define SCALE_X  4096.0f           // 2^12
#define SCALE_W  256.0f            // 2^8
#define INV_SCALE 9.5367431640625e-7f   // 2^-20

// ---------------- device scratch (bf16 tables) ----------------
__device__ __nv_bfloat16 g_Ein_h  [ITEM_NUM * 64];
__device__ __nv_bfloat16 g_Eout_h [ITEM_NUM * 64];
__device__ __nv_bfloat16 g_Ehist_h[ITEM_NUM * 128];
__device__ __nv_bfloat16 g_rin_h  [ITEM_NUM * 64];
__device__ __nv_bfloat16 g_rout_h [ITEM_NUM * 64];

// ---------------- PTX helpers ----------------
__device__ __forceinline__ uint32_t smem_u32(const void* p) {
    uint32_t a;
    asm("{ .reg .u64 t; cvta.to.shared.u64 t, %1; cvt.u32.u64 %0, t; }" : "=r"(a) : "l"(p));
    return a;
}

__device__ __forceinline__ void ldmatrix_x4(uint32_t& r0, uint32_t& r1,
                                            uint32_t& r2, uint32_t& r3,
                                            uint32_t addr) {
    asm volatile("ldmatrix.sync.aligned.m8n8.x4.shared.b16 {%0,%1,%2,%3}, [%4];"
                 : "=r"(r0), "=r"(r1), "=r"(r2), "=r"(r3) : "r"(addr));
}

__device__ __forceinline__ void mma_fp8(float& d0, float& d1, float& d2, float& d3,
                                        uint32_t a0, uint32_t a1, uint32_t a2, uint32_t a3,
                                        uint32_t b0, uint32_t b1) {
    asm volatile(
        "mma.sync.aligned.m16n8k32.row.col.f32.e4m3.e4m3.f32 "
        "{%0,%1,%2,%3}, {%4,%5,%6,%7}, {%8,%9}, {%0,%1,%2,%3};"
        : "+f"(d0), "+f"(d1), "+f"(d2), "+f"(d3)
        : "r"(a0), "r"(a1), "r"(a2), "r"(a3), "r"(b0), "r"(b1));
}

__device__ __forceinline__ uint32_t pack4_e4m3(float f0, float f1, float f2, float f3) {
    uint16_t lo, hi;
    asm("cvt.rn.satfinite.e4m3x2.f32 %0, %1, %2;" : "=h"(lo) : "f"(f1), "f"(f0));
    asm("cvt.rn.satfinite.e4m3x2.f32 %0, %1, %2;" : "=h"(hi) : "f"(f3), "f"(f2));
    return (uint32_t)lo | ((uint32_t)hi << 16);
}

__device__ __forceinline__ uint2 f4_to_bf4(float4 a) {
    __nv_bfloat162 p0 = __floats2bfloat162_rn(a.x, a.y);
    __nv_bfloat162 p1 = __floats2bfloat162_rn(a.z, a.w);
    uint2 u;
    u.x = *reinterpret_cast<uint32_t*>(&p0);
    u.y = *reinterpret_cast<uint32_t*>(&p1);
    return u;
}

__device__ __forceinline__ void mul16_store(uint4 u0, uint4 u1, const float* tg,
                                            float& dot, void* dst) {
    float x[16];
    const __nv_bfloat162* b0 = reinterpret_cast<const __nv_bfloat162*>(&u0);
    const __nv_bfloat162* b1 = reinterpret_cast<const __nv_bfloat162*>(&u1);
    #pragma unroll
    for (int i = 0; i < 4; i++) {
        float2 f = __bfloat1622float2(b0[i]);
        x[2 * i]     = f.x * tg[2 * i];
        x[2 * i + 1] = f.y * tg[2 * i + 1];
    }
    #pragma unroll
    for (int i = 0; i < 4; i++) {
        float2 f = __bfloat1622float2(b1[i]);
        x[8 + 2 * i]     = f.x * tg[8 + 2 * i];
        x[8 + 2 * i + 1] = f.y * tg[8 + 2 * i + 1];
    }
    #pragma unroll
    for (int i = 0; i < 16; i++) dot += x[i];
    uint4 o;
    o.x = pack4_e4m3(x[0] * SCALE_X,  x[1] * SCALE_X,  x[2] * SCALE_X,  x[3] * SCALE_X);
    o.y = pack4_e4m3(x[4] * SCALE_X,  x[5] * SCALE_X,  x[6] * SCALE_X,  x[7] * SCALE_X);
    o.z = pack4_e4m3(x[8] * SCALE_X,  x[9] * SCALE_X,  x[10] * SCALE_X, x[11] * SCALE_X);
    o.w = pack4_e4m3(x[12] * SCALE_X, x[13] * SCALE_X, x[14] * SCALE_X, x[15] * SCALE_X);
    *reinterpret_cast<uint4*>(dst) = o;
}

// ---------------- kernel 0: fp32 tables -> bf16 ----------------
__global__ void conv_kernel(const float* __restrict__ E_in,
                            const float* __restrict__ E_out,
                            const float* __restrict__ E_hist) {
    int i = blockIdx.x * blockDim.x + threadIdx.x;
    int stride = gridDim.x * blockDim.x;
    const float4* in4  = reinterpret_cast<const float4*>(E_in);
    const float4* out4 = reinterpret_cast<const float4*>(E_out);
    const float4* hi4  = reinterpret_cast<const float4*>(E_hist);
    uint2* din  = reinterpret_cast<uint2*>(g_Ein_h);
    uint2* dout = reinterpret_cast<uint2*>(g_Eout_h);
    uint2* dhi  = reinterpret_cast<uint2*>(g_Ehist_h);
    for (int v = i; v < ITEM_NUM * 64 / 4; v += stride) {
        din [v] = f4_to_bf4(in4 [v]);
        dout[v] = f4_to_bf4(out4[v]);
    }
    for (int v = i; v < ITEM_NUM * 128 / 4; v += stride)
        dhi[v] = f4_to_bf4(hi4[v]);
}

// ---------------- kernel A: region self-attention (parallel scores) ------
// 256 threads, 4 items per block. Warp w handles (item = w>>1, dir = w&1).
__global__ __launch_bounds__(256)
void region_kernel(const int* __restrict__ near_pois) {
    __shared__ float in_s [4][640];
    __shared__ float out_s[4][640];
    __shared__ float wo_s [4][10];
    __shared__ float wi_s [4][10];
    __shared__ int   idx_s[4][10];

    const int t    = threadIdx.x;
    const int wid  = t >> 5;
    const int lane = t & 31;
    const int nb   = blockIdx.x * 4;

    if (t < 40) idx_s[t / 10][t % 10] = near_pois[(nb + t / 10) * KN + t % 10];
    __syncthreads();

    // gather: 640 uint4 (4 items x 2 tables x 10 rows x 8 chunks), bf16 -> fp32
    #pragma unroll
    for (int w = 0; w < 3; w++) {
        int v = t + w * 256;
        if (v < 640) {
            int it = v / 160;
            int r0 = v - it * 160;
            int tb = (r0 >= 80) ? 1 : 0;
            int rr = r0 - tb * 80;
            int k = rr >> 3, c = rr & 7;
            int idx = idx_s[it][k];
            uint4 u = reinterpret_cast<const uint4*>(
                (tb ? g_Eout_h : g_Ein_h) + idx * 64)[c];
            float* dstp = (tb ? out_s[it] : in_s[it]) + k * 64 + c * 8;
            const __nv_bfloat162* bp = reinterpret_cast<const __nv_bfloat162*>(&u);
            float4 o0, o1;
            float2 f0 = __bfloat1622float2(bp[0]);
            float2 f1 = __bfloat1622float2(bp[1]);
            float2 f2 = __bfloat1622float2(bp[2]);
            float2 f3 = __bfloat1622float2(bp[3]);
            o0.x = f0.x; o0.y = f0.y; o0.z = f1.x; o0.w = f1.y;
            o1.x = f2.x; o1.y = f2.y; o1.z = f3.x; o1.w = f3.y;
            reinterpret_cast<float4*>(dstp)[0] = o0;
            reinterpret_cast<float4*>(dstp)[1] = o1;
        }
    }
    __syncthreads();

    // scores: warp w -> item w>>1, dir w&1. lane covers i = lane, lane+32.
    {
        const int it  = wid >> 1;
        const int dir = wid & 1;
        const float* qv = dir ? out_s[it] : in_s[it];
        const float* kv = dir ? in_s[it]  : out_s[it];
        float acc[KN];
        #pragma unroll
        for (int k = 0; k < KN; k++) acc[k] = 0.f;
        #pragma unroll
        for (int half = 0; half < 2; half++) {
            int i = lane + half * 32;
            float qq = qv[i];
            const float* kp = kv + i * KN;
            #pragma unroll
            for (int k = 0; k < KN; k++) acc[k] += qq * kp[k];
        }
        #pragma unroll
        for (int o = 16; o; o >>= 1)
            #pragma unroll
            for (int k = 0; k < KN; k++)
                acc[k] += __shfl_xor_sync(0xffffffffu, acc[k], o);
        if (lane < KN)
            (dir ? wi_s : wo_s)[it][lane] = expf(acc[lane] * 0.125f);
    }
    __syncthreads();

    // weighted aggregation: 4 items x 64 dims
    {
        const int it = t >> 6;
        const int d  = t & 63;
        float so = 0.f, si = 0.f;
        #pragma unroll
        for (int k = 0; k < KN; k++) { so += wo_s[it][k]; si += wi_s[it][k]; }
        float ro = 0.f, ri = 0.f;
        #pragma unroll
        for (int k = 0; k < KN; k++) {
            ro += wo_s[it][k] * out_s[it][k * 64 + d];
            ri += wi_s[it][k] * in_s [it][k * 64 + d];
        }
        g_rout_h[(nb + it) * 64 + d] = __float2bfloat16(ro / so);
        g_rin_h [(nb + it) * 64 + d] = __float2bfloat16(ri / si);
    }
}

// ---------------- main kernel: 256-row fp8 warp-MMA tiles -----------------
#define SM_X   0
#define SM_W   (MROWS * PITCH_F)                 // 69632
#define SM_AUX (SM_W + 128 * PITCH_F)            // 104448

struct Aux {
    float targ[EPT][256];
    float b1v[128];
    float w2v[128];
    float part[4][MROWS];
    float dots[MROWS];
    int   idxm[MROWS];
    int   tgv[EPT];
};
#define SMEM_TOTAL (SM_AUX + (int)sizeof(Aux))

__global__ __launch_bounds__(TB, 1)
void main_kernel(const int*   __restrict__ history,
                 const int*   __restrict__ target,
                 const float* __restrict__ E_targ,
                 const float* __restrict__ W1,
                 const float* __restrict__ b1,
                 const float* __restrict__ W2,
                 float*       __restrict__ out) {
    extern __shared__ char sm[];
    Aux* s = reinterpret_cast<Aux*>(sm + SM_AUX);
    const uint32_t sbase = smem_u32(sm);

    const int t    = threadIdx.x;
    const int wid  = t >> 5;
    const int lane = t & 31;

    const int m     = t >> 1;             // gather row (0..255)
    const int hhalf = t & 1;
    const int relem = m / 50;
    const int hrow  = m - relem * 50;

    const int wm = wid & 3;   // warp m-tile
    const int wn = wid >> 2;  // warp n-tile

    // ---- prologue ----
    {
        uint4 z = make_uint4(0, 0, 0, 0);
        for (int i = t; i < MROWS * PITCH_F / 16; i += TB)
            reinterpret_cast<uint4*>(sm + SM_X)[i] = z;
    }
    {
        const int jm = t >> 2, jq = t & 3;
        const float4* src4 = reinterpret_cast<const float4*>(W1 + jm * 256 + jq * 64);
        char* dst = sm + SM_W + jm * PITCH_F + jq * 64;
        #pragma unroll
        for (int g = 0; g < 4; g++) {
            float4 a = src4[g * 4], b = src4[g * 4 + 1];
            float4 c = src4[g * 4 + 2], e = src4[g * 4 + 3];
            uint4 u;
            u.x = pack4_e4m3(a.x * SCALE_W, a.y * SCALE_W, a.z * SCALE_W, a.w * SCALE_W);
            u.y = pack4_e4m3(b.x * SCALE_W, b.y * SCALE_W, b.z * SCALE_W, b.w * SCALE_W);
            u.z = pack4_e4m3(c.x * SCALE_W, c.y * SCALE_W, c.z * SCALE_W, c.w * SCALE_W);
            u.w = pack4_e4m3(e.x * SCALE_W, e.y * SCALE_W, e.z * SCALE_W, e.w * SCALE_W);
            *reinterpret_cast<uint4*>(dst + g * 16) = u;
        }
    }
    if (t < 128) { s->b1v[t] = b1[t]; s->w2v[t] = W2[t]; }
    __syncthreads();

    const int a_row0 = wm * 64 + ((lane >> 3) & 1) * 8 + (lane & 7);
    const uint32_t a_addr0 = sbase + SM_X + a_row0 * PITCH_F + (lane >> 4) * 16;
    const int b_row = wn * 32 + (lane >> 4) * 8 + (lane & 7);
    const uint32_t b_addr0 = sbase + SM_W + b_row * PITCH_F + ((lane >> 3) & 1) * 16;

    for (int p = blockIdx.x; p < NTILE; p += gridDim.x) {
        const bool rowvalid = (m < EPT * HIST) && (p * EPT + relem < BATCH);

        // ---- phase 0: targets + targ vectors + idx ----
        if (t < EPT) {
            int e = p * EPT + t;
            s->tgv[t] = target[e < BATCH ? e : (BATCH - 1)];
        }
        for (int v = t; v < EPT * 256; v += TB) {
            int rr = v >> 8, e = v & 255;
            int be = p * EPT + rr;
            int tg = target[be < BATCH ? be : (BATCH - 1)];
            float val;
            if (e < 128)      val = E_targ[tg * 128 + e];
            else if (e < 192) val = __bfloat162float(g_rout_h[tg * 64 + (e - 128)]);
            else              val = __bfloat162float(g_rin_h [tg * 64 + (e - 192)]);
            s->targ[rr][e] = val;
        }
        int idx = 0;
        if (hhalf == 0 && rowvalid)
            idx = history[(p * EPT + relem) * HIST + hrow];
        idx = __shfl_sync(0xffffffffu, idx, lane & ~1);
        if (hhalf == 0 && rowvalid) s->idxm[m] = idx;
        __syncthreads();

        // ---- phase 1: gather bf16, x = hist*targ -> fp8 smem; fp32 dots ----
        float dot = 0.f;
        if (rowvalid) {
            const float* tgp = &s->targ[relem][hhalf * 128];
            char* dst = sm + SM_X + m * PITCH_F + hhalf * 128;
            if (hhalf == 0) {
                const uint4* src = reinterpret_cast<const uint4*>(g_Ehist_h + idx * 128);
                #pragma unroll
                for (int g = 0; g < 8; g++)
                    mul16_store(src[2 * g], src[2 * g + 1], tgp + 16 * g, dot,
                                dst + 16 * g);
            } else {
                const uint4* s0 = reinterpret_cast<const uint4*>(g_rin_h  + idx * 64);
                const uint4* s1 = reinterpret_cast<const uint4*>(g_rout_h + idx * 64);
                #pragma unroll
                for (int g = 0; g < 4; g++)
                    mul16_store(s0[2 * g], s0[2 * g + 1], tgp + 16 * g, dot,
                                dst + 16 * g);
                #pragma unroll
                for (int g = 0; g < 4; g++)
                    mul16_store(s1[2 * g], s1[2 * g + 1], tgp + 64 + 16 * g, dot,
                                dst + 64 + 16 * g);
            }
        }
        dot += __shfl_xor_sync(0xffffffffu, dot, 1);
        if (hhalf == 0 && rowvalid) s->dots[m] = dot;
        __syncthreads();

        // ---- phase 2: warp MMA 64x32 fp8 tile ----
        float d[4][4][4];
        #pragma unroll
        for (int mf = 0; mf < 4; mf++)
            #pragma unroll
            for (int nf = 0; nf < 4; nf++)
                #pragma unroll
                for (int i = 0; i < 4; i++) d[mf][nf][i] = 0.f;

        #pragma unroll
        for (int ks = 0; ks < 8; ks++) {
            const uint32_t koff = ks * 32;
            uint32_t b0[4], b1r[4];
            ldmatrix_x4(b0[0], b0[1], b0[2], b0[3], b_addr0 + koff);
            ldmatrix_x4(b1r[0], b1r[1], b1r[2], b1r[3],
                        b_addr0 + 16 * PITCH_F + koff);
            #pragma unroll
            for (int mf = 0; mf < 4; mf++) {
                uint32_t a[4];
                ldmatrix_x4(a[0], a[1], a[2], a[3],
                            a_addr0 + mf * 16 * PITCH_F + koff);
                mma_fp8(d[mf][0][0], d[mf][0][1], d[mf][0][2], d[mf][0][3],
                        a[0], a[1], a[2], a[3], b0[0], b0[1]);
                mma_fp8(d[mf][1][0], d[mf][1][1], d[mf][1][2], d[mf][1][3],
                        a[0], a[1], a[2], a[3], b0[2], b0[3]);
                mma_fp8(d[mf][2][0], d[mf][2][1], d[mf][2][2], d[mf][2][3],
                        a[0], a[1], a[2], a[3], b1r[0], b1r[1]);
                mma_fp8(d[mf][3][0], d[mf][3][1], d[mf][3][2], d[mf][3][3],
                        a[0], a[1], a[2], a[3], b1r[2], b1r[3]);
            }
        }

        // ---- phase 3: epilogue relu(D*2^-20 + b1) * w2, reduce cols ----
        {
            float acc[4][2];
            #pragma unroll
            for (int mf = 0; mf < 4; mf++) { acc[mf][0] = 0.f; acc[mf][1] = 0.f; }
            #pragma unroll
            for (int nf = 0; nf < 4; nf++) {
                const int c0 = wn * 32 + nf * 8 + 2 * (lane & 3);
                const float bb0 = s->b1v[c0], bb1 = s->b1v[c0 + 1];
                const float ww0 = s->w2v[c0], ww1 = s->w2v[c0 + 1];
                #pragma unroll
                for (int mf = 0; mf < 4; mf++) {
                    acc[mf][0] += fmaxf(fmaf(d[mf][nf][0], INV_SCALE, bb0), 0.f) * ww0
                                + fmaxf(fmaf(d[mf][nf][1], INV_SCALE, bb1), 0.f) * ww1;
                    acc[mf][1] += fmaxf(fmaf(d[mf][nf][2], INV_SCALE, bb0), 0.f) * ww0
                                + fmaxf(fmaf(d[mf][nf][3], INV_SCALE, bb1), 0.f) * ww1;
                }
            }
            #pragma unroll
            for (int mf = 0; mf < 4; mf++) {
                #pragma unroll
                for (int i = 0; i < 2; i++) {
                    acc[mf][i] += __shfl_xor_sync(0xffffffffu, acc[mf][i], 1);
                    acc[mf][i] += __shfl_xor_sync(0xffffffffu, acc[mf][i], 2);
                }
            }
            if ((lane & 3) == 0) {
                #pragma unroll
                for (int mf = 0; mf < 4; mf++) {
                    const int row = wm * 64 + mf * 16 + (lane >> 2);
                    s->part[wn][row]     = acc[mf][0];
                    s->part[wn][row + 8] = acc[mf][1];
                }
            }
        }
        __syncthreads();

        // ---- phase 4: masked exp weighting + prediction (warp per elem) ----
        if (wid < EPT && (p * EPT + wid) < BATCH) {
            const int tg = s->tgv[wid];
            float num = 0.f, den = 0.f;
            #pragma unroll
            for (int it = 0; it < 2; it++) {
                int hh = lane + it * 32;
                if (hh < HIST) {
                    int mm = wid * HIST + hh;
                    float sc = (s->part[0][mm] + s->part[1][mm]) +
                               (s->part[2][mm] + s->part[3][mm]);
                    float e = expf(sc);
                    if (s->idxm[mm] == tg) e = 0.f;
                    num += e * s->dots[mm];
                    den += e;
                }
            }
            #pragma unroll
            for (int o = 16; o; o >>= 1) {
                num += __shfl_xor_sync(0xffffffffu, num, o);
                den += __shfl_xor_sync(0xffffffffu, den, o);
            }
            if (lane == 0) {
                float pred = num / sqrtf(den);     // BETA = 0.5
                out[p * EPT + wid] = 1.f / (1.f + expf(-pred));
            }
        }
        __syncthreads();   // protect smem reuse for next tile
    }
}

// ---------------- launch ----------------
extern "C" void kernel_launch(void* const* d_in, const int* in_sizes, int n_in,
                              void* d_out, int out_size) {
    const int*   history = (const int*)  d_in[0];
    const int*   target  = (const int*)  d_in[1];
    const int*   near_p  = (const int*)  d_in[2];
    const float* E_in    = (const float*)d_in[4];
    const float* E_out   = (const float*)d_in[5];
    const float* E_hist  = (const float*)d_in[6];
    const float* E_targ  = (const float*)d_in[7];
    const float* W1      = (const float*)d_in[8];
    const float* b1      = (const float*)d_in[9];
    const float* W2      = (const float*)d_in[10];
    float* out = (float*)d_out;

    conv_kernel<<<512, 256>>>(E_in, E_out, E_hist);
    region_kernel<<<ITEM_NUM / 4, 256>>>(near_p);

    cudaFuncSetAttribute(main_kernel,
                         cudaFuncAttributeMaxDynamicSharedMemorySize,
                         SMEM_TOTAL);
    main_kernel<<<GRID_MAIN, TB, SMEM_TOTAL>>>(history, target, E_targ,
                                               W1, b1, W2, out);
}